// round 8
// baseline (speedup 1.0000x reference)
#include <cuda_runtime.h>

#define D_MODEL 512
static constexpr float INT64_MAX_F = 9.2233720368547758e18f;

// ---------------------------------------------------------------------------
// Fused lgamma + digamma for t in [1, ~9]. Shift by 4 (y = t+4 >= 5),
// asymptotic series; recurrence product t(t+1)(t+2)(t+3) = u(u+2), u=t^2+3t.
// ---------------------------------------------------------------------------
__device__ __forceinline__ void lgamma_digamma(float t, float& lg, float& dg) {
    const float u = t * (t + 3.0f);
    const float d = u * (u + 2.0f);
    const float y = t + 4.0f;
    const float ln_y  = logf(y);
    const float inv_y = __fdividef(1.0f, y);
    const float inv2  = inv_y * inv_y;
    const float inv_d = __fdividef(1.0f, d);
    const float r    = (2.0f * t + 3.0f) * (2.0f * u + 2.0f) * inv_d;
    const float ln_p = logf(d);

    lg = fmaf(y - 0.5f, ln_y, -y) + 0.918938533204672742f
       + inv_y * (0.0833333333333f - inv2 * (0.00277777777778f - inv2 * 0.000793650793651f))
       - ln_p;
    dg = ln_y - 0.5f * inv_y
       - inv2 * (0.0833333333333f - inv2 * (0.00833333333333f - inv2 * 0.00396825396825f))
       - r;
}

// ---------------------------------------------------------------------------
// CTA-fused kernel. Each CTA owns 256 actors:
//   phase 1: each warp loops 8 groups of 4 actors (gather + dot + butterfly),
//            lanes 0..3 stash (a,bb) into smem.
//   phase 2: after one __syncthreads, all 256 threads run one actor's
//            epilogue each -- fully parallel, coalesced stores.
// The compute phase of one CTA overlaps the gather phase of other resident
// CTAs, so the epilogue cost disappears under the memory-bound gather.
// ---------------------------------------------------------------------------
__global__ void __launch_bounds__(256)
cah_kernel(const float* __restrict__ x,
           const int*   __restrict__ actors,
           const float* __restrict__ w,
           const float* __restrict__ bvec,
           const int*   __restrict__ prev,
           float*       __restrict__ out,
           int n_actors)
{
    __shared__ float2 sh_ab[256];

    const int lane  = threadIdx.x & 31;
    const int wid   = threadIdx.x >> 5;
    const int cta0  = blockIdx.x * 256;

    // Preload w into registers: lane covers columns j*128 + lane*4
    float4 w0r[4], w1r[4];
    #pragma unroll
    for (int j = 0; j < 4; j++) {
        int c = j * 128 + lane * 4;
        w0r[j] = *reinterpret_cast<const float4*>(w + c);
        w1r[j] = *reinterpret_cast<const float4*>(w + D_MODEL + c);
    }
    const float b0 = bvec[0];
    const float b1 = bvec[1];

    // ---- Phase 1: gather + dot, 8 groups of 4 actors per warp ----
    for (int g = 0; g < 8; g++) {
        const int i0 = cta0 + wid * 32 + g * 4;
        if (i0 >= n_actors) break;

        const float4* xr[4];
        #pragma unroll
        for (int q = 0; q < 4; q++) {
            const int idx = (i0 + q < n_actors) ? (i0 + q) : i0;
            const int row = __ldg(actors + idx);
            xr[q] = reinterpret_cast<const float4*>(x + (size_t)row * D_MODEL);
        }

        // 16 independent 16B gathers per lane
        float4 v[4][4];
        #pragma unroll
        for (int q = 0; q < 4; q++)
            #pragma unroll
            for (int j = 0; j < 4; j++)
                v[q][j] = __ldg(xr[q] + j * 32 + lane);

        float acc[4][2];
        #pragma unroll
        for (int q = 0; q < 4; q++) {
            float s0 = 0.0f, s1 = 0.0f;
            #pragma unroll
            for (int j = 0; j < 4; j++) {
                s0 = fmaf(v[q][j].x, w0r[j].x, s0); s0 = fmaf(v[q][j].y, w0r[j].y, s0);
                s0 = fmaf(v[q][j].z, w0r[j].z, s0); s0 = fmaf(v[q][j].w, w0r[j].w, s0);
                s1 = fmaf(v[q][j].x, w1r[j].x, s1); s1 = fmaf(v[q][j].y, w1r[j].y, s1);
                s1 = fmaf(v[q][j].z, w1r[j].z, s1); s1 = fmaf(v[q][j].w, w1r[j].w, s1);
            }
            acc[q][0] = s0; acc[q][1] = s1;
        }

        #pragma unroll
        for (int off = 16; off > 0; off >>= 1) {
            #pragma unroll
            for (int q = 0; q < 4; q++) {
                acc[q][0] += __shfl_xor_sync(0xffffffffu, acc[q][0], off);
                acc[q][1] += __shfl_xor_sync(0xffffffffu, acc[q][1], off);
            }
        }

        if (lane < 4) {
            const float z0 = acc[lane][0] + b0;
            const float z1 = acc[lane][1] + b1;
            float2 ab;
            ab.x = fmaf(z0, z0, 1.0f);
            ab.y = fmaf(z1, z1, 1.0f);
            sh_ab[wid * 32 + g * 4 + lane] = ab;
        }
    }

    __syncthreads();

    // ---- Phase 2: one actor per thread, full epilogue ----
    const int i = cta0 + threadIdx.x;
    if (i >= n_actors) return;

    const float2 ab = sh_ab[threadIdx.x];
    const float a   = ab.x;
    const float bb  = ab.y;

    const float pa     = (float)__ldg(prev + i);
    const float action = pa * (1.0f / INT64_MAX_F);

    float lga, dga, lgb, dgb, lgab, dgab;
    lgamma_digamma(a,      lga,  dga);
    lgamma_digamma(bb,     lgb,  dgb);
    lgamma_digamma(a + bb, lgab, dgab);

    const float lbeta = lga + lgb - lgab;

    const float logprob = (a - 1.0f) * logf(action)
                        + (bb - 1.0f) * log1pf(-action)
                        - lbeta;

    const float ent = lbeta
                    - (a - 1.0f)  * dga
                    - (bb - 1.0f) * dgb
                    + (a + bb - 2.0f) * dgab;

    out[i]                        = action * INT64_MAX_F;
    out[(size_t)n_actors + i]     = logprob;
    out[2 * (size_t)n_actors + i] = ent;
    float2 l; l.x = a; l.y = bb;
    *reinterpret_cast<float2*>(out + 3 * (size_t)n_actors + 2 * (size_t)i) = l;
}

extern "C" void kernel_launch(void* const* d_in, const int* in_sizes, int n_in,
                              void* d_out, int out_size)
{
    const float* x      = (const float*)d_in[0];
    const int*   actors = (const int*)  d_in[1];
    const float* w      = (const float*)d_in[2];
    const float* bvec   = (const float*)d_in[3];
    const int*   prev   = (const int*)  d_in[4];
    float*       out    = (float*)d_out;

    const int n_actors = in_sizes[1];  // 262144

    const int T      = 256;
    const int blocks = (n_actors + T - 1) / T;  // 256 actors per CTA
    cah_kernel<<<blocks, T>>>(x, actors, w, bvec, prev, out, n_actors);
}